// round 1
// baseline (speedup 1.0000x reference)
#include <cuda_runtime.h>

#define NQ 6
#define NL 3
#define DIM 64

// Weight-only part of each gate: M = RZ(w2) @ RY(w1) @ RZ(w0), complex 2x2.
// 18 gates x 4 entries (M00, M01, M10, M11).
__device__ float2 g_M[NL * NQ * 4];

__global__ void setup_gates(const float* __restrict__ w) {
    int g = threadIdx.x;             // gate index = layer*6 + qubit
    if (g >= NL * NQ) return;
    float w0 = w[g * 3 + 0];
    float w1 = w[g * 3 + 1];
    float w2 = w[g * 3 + 2];
    float s1, c1, sp, cp, sm2, cm2;
    sincosf(0.5f * w1, &s1, &c1);
    sincosf(0.5f * (w0 + w2), &sp, &cp);
    sincosf(0.5f * (w0 - w2), &sm2, &cm2);
    // M00 = c1 * e^{-i(w0+w2)/2}
    g_M[g * 4 + 0] = make_float2(c1 * cp, -c1 * sp);
    // M01 = -s1 * e^{+i(w0-w2)/2}
    g_M[g * 4 + 1] = make_float2(-s1 * cm2, -s1 * sm2);
    // M10 =  s1 * e^{-i(w0-w2)/2}
    g_M[g * 4 + 2] = make_float2(s1 * cm2, -s1 * sm2);
    // M11 = c1 * e^{+i(w0+w2)/2}
    g_M[g * 4 + 3] = make_float2(c1 * cp, c1 * sp);
}

__device__ __forceinline__ float2 cmul(float2 a, float2 b) {
    return make_float2(fmaf(a.x, b.x, -a.y * b.y),
                       fmaf(a.x, b.y,  a.y * b.x));
}

// a*b + c (complex)
__device__ __forceinline__ float2 cfma(float2 a, float2 b, float2 c) {
    float re = fmaf(a.x, b.x, fmaf(-a.y, b.y, c.x));
    float im = fmaf(a.x, b.y, fmaf( a.y, b.x, c.y));
    return make_float2(re, im);
}

// CNOT(control=c wire, target=t wire); wire w lives at bit (5-w).
__device__ __forceinline__ void cnot_gate(float2* st, int c, int t) {
    const int cb = 1 << (5 - c);
    const int tb = 1 << (5 - t);
#pragma unroll
    for (int idx = 0; idx < DIM; idx++) {
        if ((idx & cb) && !(idx & tb)) {
            float2 tmp = st[idx];
            st[idx] = st[idx | tb];
            st[idx | tb] = tmp;
        }
    }
}

__device__ __forceinline__ void cnot_ring(float2* st) {
    cnot_gate(st, 0, 1);
    cnot_gate(st, 1, 2);
    cnot_gate(st, 2, 3);
    cnot_gate(st, 3, 4);
    cnot_gate(st, 4, 5);
    cnot_gate(st, 5, 0);
}

__global__ __launch_bounds__(128, 1)
void qsim_kernel(const float* __restrict__ x, float* __restrict__ out, int B) {
    __shared__ float2 sM[NL * NQ * 4];
    if (threadIdx.x < NL * NQ * 4) sM[threadIdx.x] = g_M[threadIdx.x];
    __syncthreads();

    int b = blockIdx.x * blockDim.x + threadIdx.x;
    if (b >= B) return;

    // Per-qubit data angle: RY(pi * tanh(x_q)) -> half-angle (pi/2)*tanh(x_q)
    float cs[NQ], sn[NQ];
#pragma unroll
    for (int q = 0; q < NQ; q++) {
        float t = 1.5707963267948966f * tanhf(x[b * NQ + q]);
        __sincosf(t, &sn[q], &cs[q]);
    }

    float2 st[DIM];

    // ---- Layer 0: product-state construction (state starts at |0..0>) ----
    // v_q = first column of G_q = cs*M[:,0] + sn*M[:,1]
    {
        float2 m00 = sM[0], m01 = sM[1], m10 = sM[2], m11 = sM[3];
        st[0] = make_float2(fmaf(cs[0], m00.x, sn[0] * m01.x),
                            fmaf(cs[0], m00.y, sn[0] * m01.y));
        st[1] = make_float2(fmaf(cs[0], m10.x, sn[0] * m11.x),
                            fmaf(cs[0], m10.y, sn[0] * m11.y));
    }
#pragma unroll
    for (int q = 1; q < NQ; q++) {
        float2 m00 = sM[q * 4 + 0], m01 = sM[q * 4 + 1];
        float2 m10 = sM[q * 4 + 2], m11 = sM[q * 4 + 3];
        float2 v0 = make_float2(fmaf(cs[q], m00.x, sn[q] * m01.x),
                                fmaf(cs[q], m00.y, sn[q] * m01.y));
        float2 v1 = make_float2(fmaf(cs[q], m10.x, sn[q] * m11.x),
                                fmaf(cs[q], m10.y, sn[q] * m11.y));
#pragma unroll
        for (int k = (1 << q) - 1; k >= 0; k--) {
            float2 a = st[k];
            st[2 * k + 1] = cmul(a, v1);
            st[2 * k]     = cmul(a, v0);
        }
    }
    cnot_ring(st);

    // ---- Layers 1..2: full single-qubit gate sweeps + CNOT ring ----
#pragma unroll
    for (int layer = 1; layer < NL; layer++) {
#pragma unroll
        for (int q = 0; q < NQ; q++) {
            int gi = (layer * NQ + q) * 4;
            float2 m00 = sM[gi + 0], m01 = sM[gi + 1];
            float2 m10 = sM[gi + 2], m11 = sM[gi + 3];
            float c = cs[q], s = sn[q];
            // G = M @ RY(theta): col0 = c*M[:,0]+s*M[:,1], col1 = -s*M[:,0]+c*M[:,1]
            float2 G00 = make_float2(fmaf(c, m00.x, s * m01.x),
                                     fmaf(c, m00.y, s * m01.y));
            float2 G01 = make_float2(fmaf(-s, m00.x, c * m01.x),
                                     fmaf(-s, m00.y, c * m01.y));
            float2 G10 = make_float2(fmaf(c, m10.x, s * m11.x),
                                     fmaf(c, m10.y, s * m11.y));
            float2 G11 = make_float2(fmaf(-s, m10.x, c * m11.x),
                                     fmaf(-s, m10.y, c * m11.y));
            const int stride = 1 << (5 - q);
#pragma unroll
            for (int p = 0; p < DIM / 2; p++) {
                int i0 = ((p & ~(stride - 1)) << 1) | (p & (stride - 1));
                int i1 = i0 + stride;
                float2 a  = st[i0];
                float2 bb = st[i1];
                st[i0] = cfma(G00, a, cmul(G01, bb));
                st[i1] = cfma(G10, a, cmul(G11, bb));
            }
        }
        cnot_ring(st);
    }

    // ---- Readout: PauliZ expvals per qubit ----
    float ev[NQ] = {0.f, 0.f, 0.f, 0.f, 0.f, 0.f};
#pragma unroll
    for (int idx = 0; idx < DIM; idx++) {
        float p = fmaf(st[idx].x, st[idx].x, st[idx].y * st[idx].y);
#pragma unroll
        for (int q = 0; q < NQ; q++) {
            ev[q] += ((idx >> (5 - q)) & 1) ? -p : p;
        }
    }
#pragma unroll
    for (int q = 0; q < NQ; q++) out[b * NQ + q] = ev[q];
}

extern "C" void kernel_launch(void* const* d_in, const int* in_sizes, int n_in,
                              void* d_out, int out_size) {
    const float* x = (const float*)d_in[0];
    const float* w = (const float*)d_in[1];
    float* out = (float*)d_out;
    int B = in_sizes[0] / NQ;

    setup_gates<<<1, 32>>>(w);

    const int threads = 128;
    int blocks = (B + threads - 1) / threads;
    qsim_kernel<<<blocks, threads>>>(x, out, B);
}

// round 2
// speedup vs baseline: 1.6091x; 1.6091x over previous
#include <cuda_runtime.h>

#define NQ 6
#define NL 3

typedef unsigned long long ull;

// Weight-only part of each gate: M = RZ(w2) @ RY(w1) @ RZ(w0), complex 2x2.
__device__ float2 g_M[NL * NQ * 4];

__global__ void setup_gates(const float* __restrict__ w) {
    int g = threadIdx.x;
    if (g >= NL * NQ) return;
    float w0 = w[g * 3 + 0];
    float w1 = w[g * 3 + 1];
    float w2 = w[g * 3 + 2];
    float s1, c1, sp_, cp_, sm2, cm2;
    sincosf(0.5f * w1, &s1, &c1);
    sincosf(0.5f * (w0 + w2), &sp_, &cp_);
    sincosf(0.5f * (w0 - w2), &sm2, &cm2);
    g_M[g * 4 + 0] = make_float2(c1 * cp_, -c1 * sp_);   // M00
    g_M[g * 4 + 1] = make_float2(-s1 * cm2, -s1 * sm2);  // M01
    g_M[g * 4 + 2] = make_float2(s1 * cm2, -s1 * sm2);   // M10
    g_M[g * 4 + 3] = make_float2(c1 * cp_, c1 * sp_);    // M11
}

// ---- packed f32x2 helpers ----
__device__ __forceinline__ ull fma2(ull a, ull b, ull c) {
    ull d; asm("fma.rn.f32x2 %0,%1,%2,%3;" : "=l"(d) : "l"(a), "l"(b), "l"(c)); return d;
}
__device__ __forceinline__ ull mul2(ull a, ull b) {
    ull d; asm("mul.rn.f32x2 %0,%1,%2;" : "=l"(d) : "l"(a), "l"(b)); return d;
}
__device__ __forceinline__ ull pk(float lo, float hi) {
    ull d; asm("mov.b64 %0,{%1,%2};" : "=l"(d) : "f"(lo), "f"(hi)); return d;
}
__device__ __forceinline__ ull sp2(float x) { return pk(x, x); }
__device__ __forceinline__ float flo(ull v) { return __uint_as_float((unsigned)v); }
__device__ __forceinline__ float fhi(ull v) { return __uint_as_float((unsigned)(v >> 32)); }

// Gate on local wire w in {1..4}: pack-index stride S = 1<<(4-w). Element-wise packed.
template <int S>
__device__ __forceinline__ void gate_local(ull* RE, ull* IM,
                                           float2 G00, float2 G01, float2 G10, float2 G11) {
    ull x00 = sp2(G00.x), ny00 = sp2(-G00.y), y00 = sp2(G00.y);
    ull x01 = sp2(G01.x), ny01 = sp2(-G01.y), y01 = sp2(G01.y);
    ull x10 = sp2(G10.x), ny10 = sp2(-G10.y), y10 = sp2(G10.y);
    ull x11 = sp2(G11.x), ny11 = sp2(-G11.y), y11 = sp2(G11.y);
#pragma unroll
    for (int t = 0; t < 8; t++) {
        int K0 = ((t & ~(S - 1)) << 1) | (t & (S - 1));
        int K1 = K0 + S;
        ull r0 = RE[K0], i0 = IM[K0], r1 = RE[K1], i1 = IM[K1];
        RE[K0] = fma2(x00, r0, fma2(ny00, i0, fma2(x01, r1, mul2(ny01, i1))));
        IM[K0] = fma2(x00, i0, fma2(y00, r0, fma2(x01, i1, mul2(y01, r1))));
        RE[K1] = fma2(x10, r0, fma2(ny10, i0, fma2(x11, r1, mul2(ny11, i1))));
        IM[K1] = fma2(x10, i0, fma2(y10, r0, fma2(x11, i1, mul2(y11, r1))));
    }
}

// Gate on wire 5 (the two lanes inside each pack).
__device__ __forceinline__ void gate_w5(ull* RE, ull* IM,
                                        float2 G00, float2 G01, float2 G10, float2 G11) {
    ull P0 = pk(G00.x, G10.x), P1 = pk(-G00.y, -G10.y);
    ull P2 = pk(G01.x, G11.x), P3 = pk(-G01.y, -G11.y);
    ull Q0 = pk(G00.y, G10.y), Q2 = pk(G01.y, G11.y);
#pragma unroll
    for (int K = 0; K < 16; K++) {
        float r0 = flo(RE[K]), r1 = fhi(RE[K]);
        float i0 = flo(IM[K]), i1 = fhi(IM[K]);
        ull sr0 = sp2(r0), si0 = sp2(i0), sr1 = sp2(r1), si1 = sp2(i1);
        RE[K] = fma2(P0, sr0, fma2(P1, si0, fma2(P2, sr1, mul2(P3, si1))));
        IM[K] = fma2(Q0, sr0, fma2(P0, si0, fma2(Q2, sr1, mul2(P2, si1))));
    }
}

// Gate on wire 0 (split across the thread pair): st = Gd*st + Go*partner_st.
__device__ __forceinline__ void gate_w0(ull* RE, ull* IM, float2 Gd, float2 Go) {
    ull dx = sp2(Gd.x), ndy = sp2(-Gd.y), dy = sp2(Gd.y);
    ull ox = sp2(Go.x), noy = sp2(-Go.y), oy = sp2(Go.y);
#pragma unroll
    for (int K = 0; K < 16; K++) {
        ull ro = __shfl_xor_sync(0xffffffffu, RE[K], 1);
        ull io = __shfl_xor_sync(0xffffffffu, IM[K], 1);
        ull r = RE[K], i = IM[K];
        RE[K] = fma2(dx, r, fma2(ndy, i, fma2(ox, ro, mul2(noy, io))));
        IM[K] = fma2(dx, i, fma2(dy, r, fma2(ox, io, mul2(oy, ro))));
    }
}

__device__ __forceinline__ void swp(ull& a, ull& b) { ull t = a; a = b; b = t; }

// CNOT ring: (0,1)(1,2)(2,3)(3,4)(4,5)(5,0).
// wire0 = thread parity p; wires1..4 = pack-index bits 3..0; wire5 = lane-in-pack.
__device__ __forceinline__ void cnot_ring(ull* RE, ull* IM, int p) {
    // cnot(0,1): p==1 threads flip pack bit3
    {
        bool pb = (p != 0);
#pragma unroll
        for (int K = 0; K < 8; K++) {
            ull a = RE[K], b = RE[K + 8];
            RE[K] = pb ? b : a; RE[K + 8] = pb ? a : b;
            ull c = IM[K], d = IM[K + 8];
            IM[K] = pb ? d : c; IM[K + 8] = pb ? c : d;
        }
    }
    // cnot(1,2): bit3==1 -> flip bit2  (free renames)
    swp(RE[8], RE[12]); swp(IM[8], IM[12]);
    swp(RE[9], RE[13]); swp(IM[9], IM[13]);
    swp(RE[10], RE[14]); swp(IM[10], IM[14]);
    swp(RE[11], RE[15]); swp(IM[11], IM[15]);
    // cnot(2,3): bit2==1 -> flip bit1
    swp(RE[4], RE[6]);  swp(IM[4], IM[6]);
    swp(RE[5], RE[7]);  swp(IM[5], IM[7]);
    swp(RE[12], RE[14]); swp(IM[12], IM[14]);
    swp(RE[13], RE[15]); swp(IM[13], IM[15]);
    // cnot(3,4): bit1==1 -> flip bit0
    swp(RE[2], RE[3]);  swp(IM[2], IM[3]);
    swp(RE[6], RE[7]);  swp(IM[6], IM[7]);
    swp(RE[10], RE[11]); swp(IM[10], IM[11]);
    swp(RE[14], RE[15]); swp(IM[14], IM[15]);
    // cnot(4,5): bit0==1 -> swap the two lanes of the pack
#pragma unroll
    for (int K = 1; K < 16; K += 2) {
        RE[K] = pk(fhi(RE[K]), flo(RE[K]));
        IM[K] = pk(fhi(IM[K]), flo(IM[K]));
    }
    // cnot(5,0): hi lane (wire5=1) swaps across the thread pair
#pragma unroll
    for (int K = 0; K < 16; K++) {
        float hr = __shfl_xor_sync(0xffffffffu, fhi(RE[K]), 1);
        RE[K] = pk(flo(RE[K]), hr);
        float hi_ = __shfl_xor_sync(0xffffffffu, fhi(IM[K]), 1);
        IM[K] = pk(flo(IM[K]), hi_);
    }
}

__device__ __forceinline__ void makeG(const float2* m, float c, float s,
                                      float2& G00, float2& G01, float2& G10, float2& G11) {
    float2 m00 = m[0], m01 = m[1], m10 = m[2], m11 = m[3];
    G00.x = fmaf(c, m00.x, s * m01.x);  G00.y = fmaf(c, m00.y, s * m01.y);
    G01.x = fmaf(-s, m00.x, c * m01.x); G01.y = fmaf(-s, m00.y, c * m01.y);
    G10.x = fmaf(c, m10.x, s * m11.x);  G10.y = fmaf(c, m10.y, s * m11.y);
    G11.x = fmaf(-s, m10.x, c * m11.x); G11.y = fmaf(-s, m10.y, c * m11.y);
}

__global__ __launch_bounds__(128, 3)
void qsim_kernel(const float* __restrict__ x, float* __restrict__ out, int B) {
    __shared__ float2 sM[NL * NQ * 4];
    if (threadIdx.x < NL * NQ * 4) sM[threadIdx.x] = g_M[threadIdx.x];
    __syncthreads();

    int tid = blockIdx.x * blockDim.x + threadIdx.x;
    int b = tid >> 1;
    if (b >= B) return;
    int p = tid & 1;  // this thread's wire-0 (MSB) value

    float cs[NQ], sn[NQ];
#pragma unroll
    for (int q = 0; q < NQ; q++) {
        float t = 1.5707963267948966f * tanhf(x[b * NQ + q]);
        __sincosf(t, &sn[q], &cs[q]);
    }

    // 32 local amps packed: RE[K] = (re_{2K}, re_{2K+1}), pack lane = wire5.
    // Pack-index bits 3..0 = wires 1..4.
    ull RE[16], IM[16];

    // ---- Layer 0: product state |0..0> -> tensor of first gate columns ----
    {
        // First columns v_q0 (amp bit=0), v_q1 (amp bit=1) for each wire.
        float2 a;  // wire-0 factor for this thread
        {
            float2 m00 = sM[0], m01 = sM[1], m10 = sM[2], m11 = sM[3];
            float2 v0 = make_float2(fmaf(cs[0], m00.x, sn[0] * m01.x),
                                    fmaf(cs[0], m00.y, sn[0] * m01.y));
            float2 v1 = make_float2(fmaf(cs[0], m10.x, sn[0] * m11.x),
                                    fmaf(cs[0], m10.y, sn[0] * m11.y));
            a.x = p ? v1.x : v0.x; a.y = p ? v1.y : v0.y;
        }
        // wire-5 factor, packed across lanes
        {
            float2 m00 = sM[5 * 4 + 0], m01 = sM[5 * 4 + 1];
            float2 m10 = sM[5 * 4 + 2], m11 = sM[5 * 4 + 3];
            float2 v0 = make_float2(fmaf(cs[5], m00.x, sn[5] * m01.x),
                                    fmaf(cs[5], m00.y, sn[5] * m01.y));
            float2 v1 = make_float2(fmaf(cs[5], m10.x, sn[5] * m11.x),
                                    fmaf(cs[5], m10.y, sn[5] * m11.y));
            ull V5X = pk(v0.x, v1.x), V5Y = pk(v0.y, v1.y), V5Yn = pk(-v0.y, -v1.y);
            RE[0] = fma2(sp2(a.x), V5X, mul2(sp2(a.y), V5Yn));
            IM[0] = fma2(sp2(a.x), V5Y, mul2(sp2(a.y), V5X));
        }
        // double in wires 1..4 (packed scalar multiplies)
#pragma unroll
        for (int q = 1; q <= 4; q++) {
            float2 m00 = sM[q * 4 + 0], m01 = sM[q * 4 + 1];
            float2 m10 = sM[q * 4 + 2], m11 = sM[q * 4 + 3];
            float2 v0 = make_float2(fmaf(cs[q], m00.x, sn[q] * m01.x),
                                    fmaf(cs[q], m00.y, sn[q] * m01.y));
            float2 v1 = make_float2(fmaf(cs[q], m10.x, sn[q] * m11.x),
                                    fmaf(cs[q], m10.y, sn[q] * m11.y));
            ull x0 = sp2(v0.x), ny0 = sp2(-v0.y), y0 = sp2(v0.y);
            ull x1 = sp2(v1.x), ny1 = sp2(-v1.y), y1 = sp2(v1.y);
            int n = 1 << (q - 1);
#pragma unroll
            for (int k = 15; k >= 0; k--) {
                if (k < n) {
                    ull r = RE[k], i = IM[k];
                    RE[2 * k + 1] = fma2(x1, r, mul2(ny1, i));
                    IM[2 * k + 1] = fma2(x1, i, mul2(y1, r));
                    RE[2 * k]     = fma2(x0, r, mul2(ny0, i));
                    IM[2 * k]     = fma2(x0, i, mul2(y0, r));
                }
            }
        }
    }
    cnot_ring(RE, IM, p);

    // ---- Layers 1..2 ----
#pragma unroll
    for (int layer = 1; layer < NL; layer++) {
        const float2* mbase = &sM[layer * NQ * 4];
        float2 G00, G01, G10, G11;
        // wire 0 (cross-thread)
        makeG(mbase + 0, cs[0], sn[0], G00, G01, G10, G11);
        {
            float2 Gd, Go;
            Gd.x = p ? G11.x : G00.x; Gd.y = p ? G11.y : G00.y;
            Go.x = p ? G10.x : G01.x; Go.y = p ? G10.y : G01.y;
            gate_w0(RE, IM, Gd, Go);
        }
        // wires 1..4 (local packed)
        makeG(mbase + 4, cs[1], sn[1], G00, G01, G10, G11);
        gate_local<8>(RE, IM, G00, G01, G10, G11);
        makeG(mbase + 8, cs[2], sn[2], G00, G01, G10, G11);
        gate_local<4>(RE, IM, G00, G01, G10, G11);
        makeG(mbase + 12, cs[3], sn[3], G00, G01, G10, G11);
        gate_local<2>(RE, IM, G00, G01, G10, G11);
        makeG(mbase + 16, cs[4], sn[4], G00, G01, G10, G11);
        gate_local<1>(RE, IM, G00, G01, G10, G11);
        // wire 5 (intra-pack)
        makeG(mbase + 20, cs[5], sn[5], G00, G01, G10, G11);
        gate_w5(RE, IM, G00, G01, G10, G11);

        cnot_ring(RE, IM, p);
    }

    // ---- Readout ----
    float tot = 0.f, e1 = 0.f, e2 = 0.f, e3 = 0.f, e4 = 0.f, e5 = 0.f;
#pragma unroll
    for (int K = 0; K < 16; K++) {
        ull PR = fma2(RE[K], RE[K], mul2(IM[K], IM[K]));
        float plo = flo(PR), phi = fhi(PR);
        float s = plo + phi;
        float d = plo - phi;
        tot += s; e5 += d;
        e1 += (K & 8) ? -s : s;
        e2 += (K & 4) ? -s : s;
        e3 += (K & 2) ? -s : s;
        e4 += (K & 1) ? -s : s;
    }
    float e0 = p ? -tot : tot;
    e0 += __shfl_xor_sync(0xffffffffu, e0, 1);
    e1 += __shfl_xor_sync(0xffffffffu, e1, 1);
    e2 += __shfl_xor_sync(0xffffffffu, e2, 1);
    e3 += __shfl_xor_sync(0xffffffffu, e3, 1);
    e4 += __shfl_xor_sync(0xffffffffu, e4, 1);
    e5 += __shfl_xor_sync(0xffffffffu, e5, 1);

    float* ob = out + (size_t)b * NQ;
    if (p == 0) {
        ob[0] = e0; ob[1] = e1; ob[2] = e2;
    } else {
        ob[3] = e3; ob[4] = e4; ob[5] = e5;
    }
}

extern "C" void kernel_launch(void* const* d_in, const int* in_sizes, int n_in,
                              void* d_out, int out_size) {
    const float* x = (const float*)d_in[0];
    const float* w = (const float*)d_in[1];
    float* out = (float*)d_out;
    int B = in_sizes[0] / NQ;

    setup_gates<<<1, 32>>>(w);

    const int threads = 128;
    long long total = 2LL * B;
    int blocks = (int)((total + threads - 1) / threads);
    qsim_kernel<<<blocks, threads>>>(x, out, B);
}

// round 3
// speedup vs baseline: 1.6220x; 1.0080x over previous
#include <cuda_runtime.h>

#define NQ 6
#define NL 3

typedef unsigned long long ull;

// Weight-only part of each gate: M = RZ(w2) @ RY(w1) @ RZ(w0), complex 2x2.
__device__ float2 g_M[NL * NQ * 4];

__global__ void setup_gates(const float* __restrict__ w) {
    int g = threadIdx.x;
    if (g >= NL * NQ) return;
    float w0 = w[g * 3 + 0];
    float w1 = w[g * 3 + 1];
    float w2 = w[g * 3 + 2];
    float s1, c1, sp_, cp_, sm2, cm2;
    sincosf(0.5f * w1, &s1, &c1);
    sincosf(0.5f * (w0 + w2), &sp_, &cp_);
    sincosf(0.5f * (w0 - w2), &sm2, &cm2);
    g_M[g * 4 + 0] = make_float2(c1 * cp_, -c1 * sp_);   // M00
    g_M[g * 4 + 1] = make_float2(-s1 * cm2, -s1 * sm2);  // M01
    g_M[g * 4 + 2] = make_float2(s1 * cm2, -s1 * sm2);   // M10
    g_M[g * 4 + 3] = make_float2(c1 * cp_, c1 * sp_);    // M11
}

// ---- packed f32x2 helpers ----
__device__ __forceinline__ ull fma2(ull a, ull b, ull c) {
    ull d; asm("fma.rn.f32x2 %0,%1,%2,%3;" : "=l"(d) : "l"(a), "l"(b), "l"(c)); return d;
}
__device__ __forceinline__ ull mul2(ull a, ull b) {
    ull d; asm("mul.rn.f32x2 %0,%1,%2;" : "=l"(d) : "l"(a), "l"(b)); return d;
}
__device__ __forceinline__ ull pk(float lo, float hi) {
    ull d; asm("mov.b64 %0,{%1,%2};" : "=l"(d) : "f"(lo), "f"(hi)); return d;
}
__device__ __forceinline__ ull sp2(float x) { return pk(x, x); }
__device__ __forceinline__ float flo(ull v) { return __uint_as_float((unsigned)v); }
__device__ __forceinline__ float fhi(ull v) { return __uint_as_float((unsigned)(v >> 32)); }
// lo lane from a, hi lane from b
__device__ __forceinline__ ull mlh(ull a, ull b) { return pk(flo(a), fhi(b)); }

// Gate on local wire w in {1..4}: pack-index stride S = 1<<(4-w). Element-wise packed.
template <int S>
__device__ __forceinline__ void gate_local(ull* RE, ull* IM,
                                           float2 G00, float2 G01, float2 G10, float2 G11) {
    ull x00 = sp2(G00.x), ny00 = sp2(-G00.y), y00 = sp2(G00.y);
    ull x01 = sp2(G01.x), ny01 = sp2(-G01.y), y01 = sp2(G01.y);
    ull x10 = sp2(G10.x), ny10 = sp2(-G10.y), y10 = sp2(G10.y);
    ull x11 = sp2(G11.x), ny11 = sp2(-G11.y), y11 = sp2(G11.y);
#pragma unroll
    for (int t = 0; t < 8; t++) {
        int K0 = ((t & ~(S - 1)) << 1) | (t & (S - 1));
        int K1 = K0 + S;
        ull r0 = RE[K0], i0 = IM[K0], r1 = RE[K1], i1 = IM[K1];
        RE[K0] = fma2(x00, r0, fma2(ny00, i0, fma2(x01, r1, mul2(ny01, i1))));
        IM[K0] = fma2(x00, i0, fma2(y00, r0, fma2(x01, i1, mul2(y01, r1))));
        RE[K1] = fma2(x10, r0, fma2(ny10, i0, fma2(x11, r1, mul2(ny11, i1))));
        IM[K1] = fma2(x10, i0, fma2(y10, r0, fma2(x11, i1, mul2(y11, r1))));
    }
}

// Gate on wire 5 (the two lanes inside each pack).
__device__ __forceinline__ void gate_w5(ull* RE, ull* IM,
                                        float2 G00, float2 G01, float2 G10, float2 G11) {
    ull P0 = pk(G00.x, G10.x), P1 = pk(-G00.y, -G10.y);
    ull P2 = pk(G01.x, G11.x), P3 = pk(-G01.y, -G11.y);
    ull Q0 = pk(G00.y, G10.y), Q2 = pk(G01.y, G11.y);
#pragma unroll
    for (int K = 0; K < 16; K++) {
        float r0 = flo(RE[K]), r1 = fhi(RE[K]);
        float i0 = flo(IM[K]), i1 = fhi(IM[K]);
        ull sr0 = sp2(r0), si0 = sp2(i0), sr1 = sp2(r1), si1 = sp2(i1);
        RE[K] = fma2(P0, sr0, fma2(P1, si0, fma2(P2, sr1, mul2(P3, si1))));
        IM[K] = fma2(Q0, sr0, fma2(P0, si0, fma2(Q2, sr1, mul2(P2, si1))));
    }
}

// Gate on wire 0 fused with a PENDING cnot(5,0) from the preceding ring.
// cnot(5,0) (control=wire5, target=wire0) swaps hi-lane amps across the thread
// pair. Effective operand packs: A = (my_lo, partner_hi), B = (partner_lo, my_hi).
// out = Gd*A + Go*B  (element-wise, uniform constants).
__device__ __forceinline__ void gate_w0_fused(ull* RE, ull* IM, float2 Gd, float2 Go) {
    ull dx = sp2(Gd.x), ndy = sp2(-Gd.y), dy = sp2(Gd.y);
    ull ox = sp2(Go.x), noy = sp2(-Go.y), oy = sp2(Go.y);
#pragma unroll
    for (int K = 0; K < 16; K++) {
        ull pr = __shfl_xor_sync(0xffffffffu, RE[K], 1);
        ull pi = __shfl_xor_sync(0xffffffffu, IM[K], 1);
        ull Ar = mlh(RE[K], pr), Br = mlh(pr, RE[K]);
        ull Ai = mlh(IM[K], pi), Bi = mlh(pi, IM[K]);
        RE[K] = fma2(dx, Ar, fma2(ndy, Ai, fma2(ox, Br, mul2(noy, Bi))));
        IM[K] = fma2(dx, Ai, fma2(dy, Ar, fma2(ox, Bi, mul2(oy, Br))));
    }
}

__device__ __forceinline__ void swp(ull& a, ull& b) { ull t = a; a = b; b = t; }

// CNOT ring WITHOUT the final cnot(5,0): (0,1)(1,2)(2,3)(3,4)(4,5).
// The trailing cnot(5,0) is fused into the next wire-0 gate (or readout).
__device__ __forceinline__ void cnot_ring_partial(ull* RE, ull* IM, int p) {
    // cnot(0,1): p==1 threads flip pack bit3
    {
        bool pb = (p != 0);
#pragma unroll
        for (int K = 0; K < 8; K++) {
            ull a = RE[K], b = RE[K + 8];
            RE[K] = pb ? b : a; RE[K + 8] = pb ? a : b;
            ull c = IM[K], d = IM[K + 8];
            IM[K] = pb ? d : c; IM[K + 8] = pb ? c : d;
        }
    }
    // cnot(1,2): bit3==1 -> flip bit2  (free renames)
    swp(RE[8], RE[12]); swp(IM[8], IM[12]);
    swp(RE[9], RE[13]); swp(IM[9], IM[13]);
    swp(RE[10], RE[14]); swp(IM[10], IM[14]);
    swp(RE[11], RE[15]); swp(IM[11], IM[15]);
    // cnot(2,3): bit2==1 -> flip bit1
    swp(RE[4], RE[6]);  swp(IM[4], IM[6]);
    swp(RE[5], RE[7]);  swp(IM[5], IM[7]);
    swp(RE[12], RE[14]); swp(IM[12], IM[14]);
    swp(RE[13], RE[15]); swp(IM[13], IM[15]);
    // cnot(3,4): bit1==1 -> flip bit0
    swp(RE[2], RE[3]);  swp(IM[2], IM[3]);
    swp(RE[6], RE[7]);  swp(IM[6], IM[7]);
    swp(RE[10], RE[11]); swp(IM[10], IM[11]);
    swp(RE[14], RE[15]); swp(IM[14], IM[15]);
    // cnot(4,5): bit0==1 -> swap the two lanes of the pack
#pragma unroll
    for (int K = 1; K < 16; K += 2) {
        RE[K] = pk(fhi(RE[K]), flo(RE[K]));
        IM[K] = pk(fhi(IM[K]), flo(IM[K]));
    }
}

__device__ __forceinline__ void makeG(const float2* m, float c, float s,
                                      float2& G00, float2& G01, float2& G10, float2& G11) {
    float2 m00 = m[0], m01 = m[1], m10 = m[2], m11 = m[3];
    G00.x = fmaf(c, m00.x, s * m01.x);  G00.y = fmaf(c, m00.y, s * m01.y);
    G01.x = fmaf(-s, m00.x, c * m01.x); G01.y = fmaf(-s, m00.y, c * m01.y);
    G10.x = fmaf(c, m10.x, s * m11.x);  G10.y = fmaf(c, m10.y, s * m11.y);
    G11.x = fmaf(-s, m10.x, c * m11.x); G11.y = fmaf(-s, m10.y, c * m11.y);
}

__global__ __launch_bounds__(128, 4)
void qsim_kernel(const float* __restrict__ x, float* __restrict__ out, int B) {
    __shared__ float2 sM[NL * NQ * 4];
    if (threadIdx.x < NL * NQ * 4) sM[threadIdx.x] = g_M[threadIdx.x];
    __syncthreads();

    int tid = blockIdx.x * blockDim.x + threadIdx.x;
    int b = tid >> 1;
    if (b >= B) return;
    int p = tid & 1;  // this thread's wire-0 (MSB) value

    float cs[NQ], sn[NQ];
#pragma unroll
    for (int q = 0; q < NQ; q++) {
        float t = 1.5707963267948966f * tanhf(x[b * NQ + q]);
        __sincosf(t, &sn[q], &cs[q]);
    }

    // 32 local amps packed: RE[K] = (re_{2K}, re_{2K+1}), pack lane = wire5.
    // Pack-index bits 3..0 = wires 1..4.
    ull RE[16], IM[16];

    // ---- Layer 0: product state |0..0> -> tensor of first gate columns ----
    {
        float2 a;  // wire-0 factor for this thread
        {
            float2 m00 = sM[0], m01 = sM[1], m10 = sM[2], m11 = sM[3];
            float2 v0 = make_float2(fmaf(cs[0], m00.x, sn[0] * m01.x),
                                    fmaf(cs[0], m00.y, sn[0] * m01.y));
            float2 v1 = make_float2(fmaf(cs[0], m10.x, sn[0] * m11.x),
                                    fmaf(cs[0], m10.y, sn[0] * m11.y));
            a.x = p ? v1.x : v0.x; a.y = p ? v1.y : v0.y;
        }
        {
            float2 m00 = sM[5 * 4 + 0], m01 = sM[5 * 4 + 1];
            float2 m10 = sM[5 * 4 + 2], m11 = sM[5 * 4 + 3];
            float2 v0 = make_float2(fmaf(cs[5], m00.x, sn[5] * m01.x),
                                    fmaf(cs[5], m00.y, sn[5] * m01.y));
            float2 v1 = make_float2(fmaf(cs[5], m10.x, sn[5] * m11.x),
                                    fmaf(cs[5], m10.y, sn[5] * m11.y));
            ull V5X = pk(v0.x, v1.x), V5Y = pk(v0.y, v1.y), V5Yn = pk(-v0.y, -v1.y);
            RE[0] = fma2(sp2(a.x), V5X, mul2(sp2(a.y), V5Yn));
            IM[0] = fma2(sp2(a.x), V5Y, mul2(sp2(a.y), V5X));
        }
#pragma unroll
        for (int q = 1; q <= 4; q++) {
            float2 m00 = sM[q * 4 + 0], m01 = sM[q * 4 + 1];
            float2 m10 = sM[q * 4 + 2], m11 = sM[q * 4 + 3];
            float2 v0 = make_float2(fmaf(cs[q], m00.x, sn[q] * m01.x),
                                    fmaf(cs[q], m00.y, sn[q] * m01.y));
            float2 v1 = make_float2(fmaf(cs[q], m10.x, sn[q] * m11.x),
                                    fmaf(cs[q], m10.y, sn[q] * m11.y));
            ull x0 = sp2(v0.x), ny0 = sp2(-v0.y), y0 = sp2(v0.y);
            ull x1 = sp2(v1.x), ny1 = sp2(-v1.y), y1 = sp2(v1.y);
            int n = 1 << (q - 1);
#pragma unroll
            for (int k = 15; k >= 0; k--) {
                if (k < n) {
                    ull r = RE[k], i = IM[k];
                    RE[2 * k + 1] = fma2(x1, r, mul2(ny1, i));
                    IM[2 * k + 1] = fma2(x1, i, mul2(y1, r));
                    RE[2 * k]     = fma2(x0, r, mul2(ny0, i));
                    IM[2 * k]     = fma2(x0, i, mul2(y0, r));
                }
            }
        }
    }
    cnot_ring_partial(RE, IM, p);  // cnot(5,0) pending -> fused into next gate_w0

    // ---- Layers 1..2 ----
#pragma unroll
    for (int layer = 1; layer < NL; layer++) {
        const float2* mbase = &sM[layer * NQ * 4];
        float2 G00, G01, G10, G11;
        // wire 0 (cross-thread), fused with pending cnot(5,0)
        makeG(mbase + 0, cs[0], sn[0], G00, G01, G10, G11);
        {
            float2 Gd, Go;
            Gd.x = p ? G11.x : G00.x; Gd.y = p ? G11.y : G00.y;
            Go.x = p ? G10.x : G01.x; Go.y = p ? G10.y : G01.y;
            gate_w0_fused(RE, IM, Gd, Go);
        }
        // wires 1..4 (local packed)
        makeG(mbase + 4, cs[1], sn[1], G00, G01, G10, G11);
        gate_local<8>(RE, IM, G00, G01, G10, G11);
        makeG(mbase + 8, cs[2], sn[2], G00, G01, G10, G11);
        gate_local<4>(RE, IM, G00, G01, G10, G11);
        makeG(mbase + 12, cs[3], sn[3], G00, G01, G10, G11);
        gate_local<2>(RE, IM, G00, G01, G10, G11);
        makeG(mbase + 16, cs[4], sn[4], G00, G01, G10, G11);
        gate_local<1>(RE, IM, G00, G01, G10, G11);
        // wire 5 (intra-pack)
        makeG(mbase + 20, cs[5], sn[5], G00, G01, G10, G11);
        gate_w5(RE, IM, G00, G01, G10, G11);

        cnot_ring_partial(RE, IM, p);  // cnot(5,0) pending again
    }

    // ---- Readout (final cnot(5,0) folded into the e0 sign) ----
    // Pending cnot(5,0): hi-lane amps have wire0 flipped relative to thread parity.
    float dsum = 0.f, e1 = 0.f, e2 = 0.f, e3 = 0.f, e4 = 0.f;
#pragma unroll
    for (int K = 0; K < 16; K++) {
        ull PR = fma2(RE[K], RE[K], mul2(IM[K], IM[K]));
        float plo = flo(PR), phi = fhi(PR);
        float s = plo + phi;
        float d = plo - phi;
        dsum += d;
        e1 += (K & 8) ? -s : s;
        e2 += (K & 4) ? -s : s;
        e3 += (K & 2) ? -s : s;
        e4 += (K & 1) ? -s : s;
    }
    float e0 = p ? -dsum : dsum;  // lo lane: wire0 = p; hi lane: wire0 = 1-p
    float e5 = dsum;              // wire5 = lane, unaffected by cnot(5,0)
    e0 += __shfl_xor_sync(0xffffffffu, e0, 1);
    e1 += __shfl_xor_sync(0xffffffffu, e1, 1);
    e2 += __shfl_xor_sync(0xffffffffu, e2, 1);
    e3 += __shfl_xor_sync(0xffffffffu, e3, 1);
    e4 += __shfl_xor_sync(0xffffffffu, e4, 1);
    e5 += __shfl_xor_sync(0xffffffffu, e5, 1);

    float* ob = out + (size_t)b * NQ;
    if (p == 0) {
        ob[0] = e0; ob[1] = e1; ob[2] = e2;
    } else {
        ob[3] = e3; ob[4] = e4; ob[5] = e5;
    }
}

extern "C" void kernel_launch(void* const* d_in, const int* in_sizes, int n_in,
                              void* d_out, int out_size) {
    const float* x = (const float*)d_in[0];
    const float* w = (const float*)d_in[1];
    float* out = (float*)d_out;
    int B = in_sizes[0] / NQ;

    setup_gates<<<1, 32>>>(w);

    const int threads = 128;
    long long total = 2LL * B;
    int blocks = (int)((total + threads - 1) / threads);
    qsim_kernel<<<blocks, threads>>>(x, out, B);
}

// round 4
// speedup vs baseline: 1.7539x; 1.0813x over previous
#include <cuda_runtime.h>

#define NQ 6
#define NL 3

typedef unsigned long long ull;

// Weight-only part of each gate: M = RZ(w2) @ RY(w1) @ RZ(w0), complex 2x2.
__device__ float2 g_M[NL * NQ * 4];

__global__ void setup_gates(const float* __restrict__ w) {
    int g = threadIdx.x;
    if (g >= NL * NQ) return;
    float w0 = w[g * 3 + 0];
    float w1 = w[g * 3 + 1];
    float w2 = w[g * 3 + 2];
    float s1, c1, sp_, cp_, sm2, cm2;
    sincosf(0.5f * w1, &s1, &c1);
    sincosf(0.5f * (w0 + w2), &sp_, &cp_);
    sincosf(0.5f * (w0 - w2), &sm2, &cm2);
    g_M[g * 4 + 0] = make_float2(c1 * cp_, -c1 * sp_);   // M00
    g_M[g * 4 + 1] = make_float2(-s1 * cm2, -s1 * sm2);  // M01
    g_M[g * 4 + 2] = make_float2(s1 * cm2, -s1 * sm2);   // M10
    g_M[g * 4 + 3] = make_float2(c1 * cp_, c1 * sp_);    // M11
}

// ---- packed f32x2 helpers ----
__device__ __forceinline__ ull fma2(ull a, ull b, ull c) {
    ull d; asm("fma.rn.f32x2 %0,%1,%2,%3;" : "=l"(d) : "l"(a), "l"(b), "l"(c)); return d;
}
__device__ __forceinline__ ull mul2(ull a, ull b) {
    ull d; asm("mul.rn.f32x2 %0,%1,%2;" : "=l"(d) : "l"(a), "l"(b)); return d;
}
__device__ __forceinline__ ull pk(float lo, float hi) {
    ull d; asm("mov.b64 %0,{%1,%2};" : "=l"(d) : "f"(lo), "f"(hi)); return d;
}
__device__ __forceinline__ ull sp2(float x) { return pk(x, x); }
__device__ __forceinline__ float flo(ull v) { return __uint_as_float((unsigned)v); }
__device__ __forceinline__ float fhi(ull v) { return __uint_as_float((unsigned)(v >> 32)); }
__device__ __forceinline__ ull lsw(ull v) { return pk(fhi(v), flo(v)); }  // lane swap
__device__ __forceinline__ float tanh_fast(float x) {
    float y; asm("tanh.approx.f32 %0, %1;" : "=f"(y) : "f"(x)); return y;
}

// Gate on local wire w in {1..4}: pack-index stride S = 1<<(4-w). Element-wise packed.
template <int S>
__device__ __forceinline__ void gate_local(ull* RE, ull* IM,
                                           float2 G00, float2 G01, float2 G10, float2 G11) {
    ull x00 = sp2(G00.x), ny00 = sp2(-G00.y), y00 = sp2(G00.y);
    ull x01 = sp2(G01.x), ny01 = sp2(-G01.y), y01 = sp2(G01.y);
    ull x10 = sp2(G10.x), ny10 = sp2(-G10.y), y10 = sp2(G10.y);
    ull x11 = sp2(G11.x), ny11 = sp2(-G11.y), y11 = sp2(G11.y);
#pragma unroll
    for (int t = 0; t < 8; t++) {
        int K0 = ((t & ~(S - 1)) << 1) | (t & (S - 1));
        int K1 = K0 + S;
        ull r0 = RE[K0], i0 = IM[K0], r1 = RE[K1], i1 = IM[K1];
        RE[K0] = fma2(x00, r0, fma2(ny00, i0, fma2(x01, r1, mul2(ny01, i1))));
        IM[K0] = fma2(x00, i0, fma2(y00, r0, fma2(x01, i1, mul2(y01, r1))));
        RE[K1] = fma2(x10, r0, fma2(ny10, i0, fma2(x11, r1, mul2(ny11, i1))));
        IM[K1] = fma2(x10, i0, fma2(y10, r0, fma2(x11, i1, mul2(y11, r1))));
    }
}

// Gate on wire 5 (the two lanes inside each pack), swap-form:
// out = P .* st + Q .* laneswap(st), P=(G00,G11), Q=(G01,G10).
__device__ __forceinline__ void gate_w5(ull* RE, ull* IM,
                                        float2 G00, float2 G01, float2 G10, float2 G11) {
    ull Px = pk(G00.x, G11.x), Py = pk(G00.y, G11.y), nPy = pk(-G00.y, -G11.y);
    ull Qx = pk(G01.x, G10.x), Qy = pk(G01.y, G10.y), nQy = pk(-G01.y, -G10.y);
#pragma unroll
    for (int K = 0; K < 16; K++) {
        ull r = RE[K], i = IM[K];
        ull rs = lsw(r), is = lsw(i);
        RE[K] = fma2(Px, r, fma2(nPy, i, fma2(Qx, rs, mul2(nQy, is))));
        IM[K] = fma2(Px, i, fma2(Py, r, fma2(Qx, is, mul2(Qy, rs))));
    }
}

// Gate on wire 0 fused with a PENDING cnot(5,0) from the preceding ring.
// The cnot(5,0) lane merge is absorbed into asymmetric coefficient packs:
//   out = pk(Gd,Go) .* mine + pk(Go,Gd) .* partner     (no lane merges needed)
__device__ __forceinline__ void gate_w0_fused(ull* RE, ull* IM, float2 Gd, float2 Go) {
    ull dx = pk(Gd.x, Go.x), ox = pk(Go.x, Gd.x);
    ull dy = pk(Gd.y, Go.y), oy = pk(Go.y, Gd.y);
    ull ndy = pk(-Gd.y, -Go.y), noy = pk(-Go.y, -Gd.y);
#pragma unroll
    for (int K = 0; K < 16; K++) {
        ull pr = __shfl_xor_sync(0xffffffffu, RE[K], 1);
        ull pi = __shfl_xor_sync(0xffffffffu, IM[K], 1);
        ull r = RE[K], i = IM[K];
        RE[K] = fma2(dx, r, fma2(ndy, i, fma2(ox, pr, mul2(noy, pi))));
        IM[K] = fma2(dx, i, fma2(dy, r, fma2(ox, pi, mul2(oy, pr))));
    }
}

__device__ __forceinline__ void swp(ull& a, ull& b) { ull t = a; a = b; b = t; }

// CNOT ring WITHOUT the final cnot(5,0): (0,1)(1,2)(2,3)(3,4)(4,5).
// The trailing cnot(5,0) is fused into the next wire-0 gate (or readout).
__device__ __forceinline__ void cnot_ring_partial(ull* RE, ull* IM, int p) {
    // cnot(0,1): p==1 threads flip pack bit3
    {
        bool pb = (p != 0);
#pragma unroll
        for (int K = 0; K < 8; K++) {
            ull a = RE[K], b = RE[K + 8];
            RE[K] = pb ? b : a; RE[K + 8] = pb ? a : b;
            ull c = IM[K], d = IM[K + 8];
            IM[K] = pb ? d : c; IM[K + 8] = pb ? c : d;
        }
    }
    // cnot(1,2): bit3==1 -> flip bit2  (free renames)
    swp(RE[8], RE[12]); swp(IM[8], IM[12]);
    swp(RE[9], RE[13]); swp(IM[9], IM[13]);
    swp(RE[10], RE[14]); swp(IM[10], IM[14]);
    swp(RE[11], RE[15]); swp(IM[11], IM[15]);
    // cnot(2,3): bit2==1 -> flip bit1
    swp(RE[4], RE[6]);  swp(IM[4], IM[6]);
    swp(RE[5], RE[7]);  swp(IM[5], IM[7]);
    swp(RE[12], RE[14]); swp(IM[12], IM[14]);
    swp(RE[13], RE[15]); swp(IM[13], IM[15]);
    // cnot(3,4): bit1==1 -> flip bit0
    swp(RE[2], RE[3]);  swp(IM[2], IM[3]);
    swp(RE[6], RE[7]);  swp(IM[6], IM[7]);
    swp(RE[10], RE[11]); swp(IM[10], IM[11]);
    swp(RE[14], RE[15]); swp(IM[14], IM[15]);
    // cnot(4,5): bit0==1 -> swap the two lanes of the pack
#pragma unroll
    for (int K = 1; K < 16; K += 2) {
        RE[K] = lsw(RE[K]);
        IM[K] = lsw(IM[K]);
    }
}

__device__ __forceinline__ void makeG(const float2* m, float c, float s,
                                      float2& G00, float2& G01, float2& G10, float2& G11) {
    float2 m00 = m[0], m01 = m[1], m10 = m[2], m11 = m[3];
    G00.x = fmaf(c, m00.x, s * m01.x);  G00.y = fmaf(c, m00.y, s * m01.y);
    G01.x = fmaf(-s, m00.x, c * m01.x); G01.y = fmaf(-s, m00.y, c * m01.y);
    G10.x = fmaf(c, m10.x, s * m11.x);  G10.y = fmaf(c, m10.y, s * m11.y);
    G11.x = fmaf(-s, m10.x, c * m11.x); G11.y = fmaf(-s, m10.y, c * m11.y);
}

__global__ __launch_bounds__(128, 4)
void qsim_kernel(const float* __restrict__ x, float* __restrict__ out, int B) {
    __shared__ float2 sM[NL * NQ * 4];
    if (threadIdx.x < NL * NQ * 4) sM[threadIdx.x] = g_M[threadIdx.x];
    __syncthreads();

    int tid = blockIdx.x * blockDim.x + threadIdx.x;
    int b = tid >> 1;
    if (b >= B) return;
    int p = tid & 1;  // this thread's wire-0 (MSB) value

    float cs[NQ], sn[NQ];
#pragma unroll
    for (int q = 0; q < NQ; q++) {
        float t = 1.5707963267948966f * tanh_fast(x[b * NQ + q]);
        __sincosf(t, &sn[q], &cs[q]);
    }

    // 32 local amps packed: RE[K] = (re_{2K}, re_{2K+1}), pack lane = wire5.
    // Pack-index bits 3..0 = wires 1..4.
    ull RE[16], IM[16];

    // ---- Layer 0: product state |0..0> -> tensor of first gate columns ----
    {
        float2 a;  // wire-0 factor for this thread
        {
            float2 m00 = sM[0], m01 = sM[1], m10 = sM[2], m11 = sM[3];
            float2 v0 = make_float2(fmaf(cs[0], m00.x, sn[0] * m01.x),
                                    fmaf(cs[0], m00.y, sn[0] * m01.y));
            float2 v1 = make_float2(fmaf(cs[0], m10.x, sn[0] * m11.x),
                                    fmaf(cs[0], m10.y, sn[0] * m11.y));
            a.x = p ? v1.x : v0.x; a.y = p ? v1.y : v0.y;
        }
        {
            float2 m00 = sM[5 * 4 + 0], m01 = sM[5 * 4 + 1];
            float2 m10 = sM[5 * 4 + 2], m11 = sM[5 * 4 + 3];
            float2 v0 = make_float2(fmaf(cs[5], m00.x, sn[5] * m01.x),
                                    fmaf(cs[5], m00.y, sn[5] * m01.y));
            float2 v1 = make_float2(fmaf(cs[5], m10.x, sn[5] * m11.x),
                                    fmaf(cs[5], m10.y, sn[5] * m11.y));
            ull V5X = pk(v0.x, v1.x), V5Y = pk(v0.y, v1.y), V5Yn = pk(-v0.y, -v1.y);
            RE[0] = fma2(sp2(a.x), V5X, mul2(sp2(a.y), V5Yn));
            IM[0] = fma2(sp2(a.x), V5Y, mul2(sp2(a.y), V5X));
        }
#pragma unroll
        for (int q = 1; q <= 4; q++) {
            float2 m00 = sM[q * 4 + 0], m01 = sM[q * 4 + 1];
            float2 m10 = sM[q * 4 + 2], m11 = sM[q * 4 + 3];
            float2 v0 = make_float2(fmaf(cs[q], m00.x, sn[q] * m01.x),
                                    fmaf(cs[q], m00.y, sn[q] * m01.y));
            float2 v1 = make_float2(fmaf(cs[q], m10.x, sn[q] * m11.x),
                                    fmaf(cs[q], m10.y, sn[q] * m11.y));
            ull x0 = sp2(v0.x), ny0 = sp2(-v0.y), y0 = sp2(v0.y);
            ull x1 = sp2(v1.x), ny1 = sp2(-v1.y), y1 = sp2(v1.y);
            int n = 1 << (q - 1);
#pragma unroll
            for (int k = 15; k >= 0; k--) {
                if (k < n) {
                    ull r = RE[k], i = IM[k];
                    RE[2 * k + 1] = fma2(x1, r, mul2(ny1, i));
                    IM[2 * k + 1] = fma2(x1, i, mul2(y1, r));
                    RE[2 * k]     = fma2(x0, r, mul2(ny0, i));
                    IM[2 * k]     = fma2(x0, i, mul2(y0, r));
                }
            }
        }
    }
    cnot_ring_partial(RE, IM, p);  // cnot(5,0) pending -> fused into next gate_w0

    // ---- Layers 1..2 ----
#pragma unroll
    for (int layer = 1; layer < NL; layer++) {
        const float2* mbase = &sM[layer * NQ * 4];
        float2 G00, G01, G10, G11;
        // wire 0 (cross-thread), fused with pending cnot(5,0).
        // Only row p of G is needed: from row entries a=m[2p], b=m[2p+1]:
        //   u = c*a + s*b, v = -s*a + c*b; Gd = p?v:u, Go = p?u:v.
        {
            float2 ma = p ? mbase[2] : mbase[0];
            float2 mb = p ? mbase[3] : mbase[1];
            float c = cs[0], s = sn[0];
            float2 u = make_float2(fmaf(c, ma.x, s * mb.x), fmaf(c, ma.y, s * mb.y));
            float2 v = make_float2(fmaf(-s, ma.x, c * mb.x), fmaf(-s, ma.y, c * mb.y));
            float2 Gd = p ? v : u;
            float2 Go = p ? u : v;
            gate_w0_fused(RE, IM, Gd, Go);
        }
        // wires 1..4 (local packed)
        makeG(mbase + 4, cs[1], sn[1], G00, G01, G10, G11);
        gate_local<8>(RE, IM, G00, G01, G10, G11);
        makeG(mbase + 8, cs[2], sn[2], G00, G01, G10, G11);
        gate_local<4>(RE, IM, G00, G01, G10, G11);
        makeG(mbase + 12, cs[3], sn[3], G00, G01, G10, G11);
        gate_local<2>(RE, IM, G00, G01, G10, G11);
        makeG(mbase + 16, cs[4], sn[4], G00, G01, G10, G11);
        gate_local<1>(RE, IM, G00, G01, G10, G11);
        // wire 5 (intra-pack, swap-form)
        makeG(mbase + 20, cs[5], sn[5], G00, G01, G10, G11);
        gate_w5(RE, IM, G00, G01, G10, G11);

        cnot_ring_partial(RE, IM, p);  // cnot(5,0) pending again
    }

    // ---- Readout (final cnot(5,0) folded into the e0 sign), packed accumulation ----
    const ull ONE = sp2(1.0f), MONE = sp2(-1.0f);
    ull At = sp2(0.0f), A1 = At, A2 = At, A3 = At, A4 = At;
#pragma unroll
    for (int K = 0; K < 16; K++) {
        ull PR = fma2(RE[K], RE[K], mul2(IM[K], IM[K]));
        At = fma2(ONE, PR, At);
        A1 = fma2((K & 8) ? MONE : ONE, PR, A1);
        A2 = fma2((K & 4) ? MONE : ONE, PR, A2);
        A3 = fma2((K & 2) ? MONE : ONE, PR, A3);
        A4 = fma2((K & 1) ? MONE : ONE, PR, A4);
    }
    float dsum = flo(At) - fhi(At);
    float e0 = p ? -dsum : dsum;  // lo lane: wire0 = p; hi lane: wire0 = 1-p
    float e5 = dsum;              // wire5 = lane, unaffected by cnot(5,0)
    float e1 = flo(A1) + fhi(A1);
    float e2 = flo(A2) + fhi(A2);
    float e3 = flo(A3) + fhi(A3);
    float e4 = flo(A4) + fhi(A4);
    e0 += __shfl_xor_sync(0xffffffffu, e0, 1);
    e1 += __shfl_xor_sync(0xffffffffu, e1, 1);
    e2 += __shfl_xor_sync(0xffffffffu, e2, 1);
    e3 += __shfl_xor_sync(0xffffffffu, e3, 1);
    e4 += __shfl_xor_sync(0xffffffffu, e4, 1);
    e5 += __shfl_xor_sync(0xffffffffu, e5, 1);

    float* ob = out + (size_t)b * NQ;
    if (p == 0) {
        ob[0] = e0; ob[1] = e1; ob[2] = e2;
    } else {
        ob[3] = e3; ob[4] = e4; ob[5] = e5;
    }
}

extern "C" void kernel_launch(void* const* d_in, const int* in_sizes, int n_in,
                              void* d_out, int out_size) {
    const float* x = (const float*)d_in[0];
    const float* w = (const float*)d_in[1];
    float* out = (float*)d_out;
    int B = in_sizes[0] / NQ;

    setup_gates<<<1, 32>>>(w);

    const int threads = 128;
    long long total = 2LL * B;
    int blocks = (int)((total + threads - 1) / threads);
    qsim_kernel<<<blocks, threads>>>(x, out, B);
}